// round 2
// baseline (speedup 1.0000x reference)
#include <cuda_runtime.h>

// KMeans label assignment: out[i] = (float) argmin_k ||x_i - c_k||^2
// N = 500000, D = 64, K = 512. fp32, FFMA-bound baseline.
// Output buffer is float32 per harness metadata (labels stored as floats).
//
// score(i,k) = ||c_k||^2 - 2 * <x_i, c_k>   (x^2 term constant per point,
// max(d2,0) clamp irrelevant for argmin).

#define DIM      64
#define D4       16            // DIM / 4
#define KCENT    512
#define KCHUNK   128           // centroids per smem chunk (32 KB, < 48 KB limit)
#define NCHUNK   (KCENT / KCHUNK)
#define THREADS  256
#define PPT      2             // points per thread
#define PPB      (THREADS * PPT)

__global__ __launch_bounds__(THREADS, 1)
void kmeans_label_kernel(const float* __restrict__ x,
                         const float* __restrict__ cent,
                         float* __restrict__ out, int n)
{
    __shared__ float4 sc[KCHUNK * D4];   // 32 KB centroid chunk
    __shared__ float  sc2[KCHUNK];       // ||c||^2 for chunk

    const int tid = threadIdx.x;
    const int i0  = blockIdx.x * PPB + tid;
    const int i1  = i0 + THREADS;
    const bool v0 = (i0 < n);
    const bool v1 = (i1 < n);

    // Load both points fully into registers (2 * 16 float4 = 128 regs).
    float4 xa[D4], xb[D4];
    {
        const float4* xp0 = reinterpret_cast<const float4*>(x + (size_t)i0 * DIM);
        const float4* xp1 = reinterpret_cast<const float4*>(x + (size_t)i1 * DIM);
        const float4 z = make_float4(0.f, 0.f, 0.f, 0.f);
#pragma unroll
        for (int d = 0; d < D4; d++) {
            xa[d] = v0 ? xp0[d] : z;
            xb[d] = v1 ? xp1[d] : z;
        }
    }

    float best0 = 3.4e38f, best1 = 3.4e38f;
    int   bi0 = 0, bi1 = 0;

    for (int ch = 0; ch < NCHUNK; ch++) {
        __syncthreads();   // protect smem reuse across chunks
        // Stage centroid chunk: KCHUNK*D4 = 2048 float4, 8 per thread, coalesced.
        {
            const float4* cg =
                reinterpret_cast<const float4*>(cent + (size_t)ch * KCHUNK * DIM);
#pragma unroll
            for (int t = 0; t < (KCHUNK * D4) / THREADS; t++)
                sc[t * THREADS + tid] = cg[t * THREADS + tid];
        }
        __syncthreads();

        // ||c||^2 per row of this chunk (128 rows; threads 0..127).
        if (tid < KCHUNK) {
            const float4* row = &sc[tid * D4];
            float s = 0.f;
#pragma unroll
            for (int d = 0; d < D4; d++) {
                float4 c = row[d];
                s = fmaf(c.x, c.x, s);
                s = fmaf(c.y, c.y, s);
                s = fmaf(c.z, c.z, s);
                s = fmaf(c.w, c.w, s);
            }
            sc2[tid] = s;
        }
        __syncthreads();

        // Main loop: 2 centroids x 2 points per iteration.
        // 256 FFMA + 32 broadcast LDS.128 per iteration; 4 independent
        // accumulator chains (dependent-FMA spacing 8 cyc > lat 4).
        for (int k = 0; k < KCHUNK; k += 2) {
            const float4* r0 = &sc[(k + 0) * D4];
            const float4* r1 = &sc[(k + 1) * D4];
            float a00 = 0.f, a01 = 0.f, a10 = 0.f, a11 = 0.f;
#pragma unroll
            for (int d = 0; d < D4; d++) {
                const float4 c0 = r0[d];
                const float4 c1 = r1[d];
                const float4 p  = xa[d];
                const float4 q  = xb[d];
                a00 = fmaf(p.x, c0.x, a00);
                a01 = fmaf(p.x, c1.x, a01);
                a10 = fmaf(q.x, c0.x, a10);
                a11 = fmaf(q.x, c1.x, a11);
                a00 = fmaf(p.y, c0.y, a00);
                a01 = fmaf(p.y, c1.y, a01);
                a10 = fmaf(q.y, c0.y, a10);
                a11 = fmaf(q.y, c1.y, a11);
                a00 = fmaf(p.z, c0.z, a00);
                a01 = fmaf(p.z, c1.z, a01);
                a10 = fmaf(q.z, c0.z, a10);
                a11 = fmaf(q.z, c1.z, a11);
                a00 = fmaf(p.w, c0.w, a00);
                a01 = fmaf(p.w, c1.w, a01);
                a10 = fmaf(q.w, c0.w, a10);
                a11 = fmaf(q.w, c1.w, a11);
            }
            const float c2k0 = sc2[k + 0];
            const float c2k1 = sc2[k + 1];
            const float s00 = fmaf(-2.f, a00, c2k0);
            const float s01 = fmaf(-2.f, a01, c2k1);
            const float s10 = fmaf(-2.f, a10, c2k0);
            const float s11 = fmaf(-2.f, a11, c2k1);
            const int kg = ch * KCHUNK + k;
            // strict < + ascending k  ==> first-occurrence argmin (matches jnp)
            if (s00 < best0) { best0 = s00; bi0 = kg;     }
            if (s01 < best0) { best0 = s01; bi0 = kg + 1; }
            if (s10 < best1) { best1 = s10; bi1 = kg;     }
            if (s11 < best1) { best1 = s11; bi1 = kg + 1; }
        }
    }

    // Output buffer is float32: store labels as floats.
    if (v0) out[i0] = (float)bi0;
    if (v1) out[i1] = (float)bi1;
}

extern "C" void kernel_launch(void* const* d_in, const int* in_sizes, int n_in,
                              void* d_out, int out_size)
{
    const float* x = (const float*)d_in[0];          // [N, 64] fp32
    const float* c = (const float*)d_in[1];          // [512, 64] fp32
    float* out = (float*)d_out;                      // [N] labels as float32

    const int n = in_sizes[0] / DIM;                 // 500000
    const int grid = (n + PPB - 1) / PPB;            // 977 CTAs

    kmeans_label_kernel<<<grid, THREADS>>>(x, c, out, n);
}

// round 4
// speedup vs baseline: 1.5729x; 1.5729x over previous
#include <cuda_runtime.h>
#include <cstdint>

// KMeans labels via legacy tensor-core mma.sync (tf32, sm_80+ PTX -> works on
// compute_103 virtual arch; tcgen05 is blocked by harness PTX target).
//
// score(i,k) = ||c_k||^2 - 2<x_i,c_k>.  Centroids pre-scaled by -2 and split
// into tf32 (h + l); x split likewise; products hh + hl + lh accumulated in
// fp32 on top of acc initialized with ||c||^2.  Dot error ~4e-6 << fp32 noise.

#define DIM      64
#define KCENT    512
#define TILE_M   128
#define CHN      128          // centroids per chunk
#define THREADS  256

// dynamic smem layout (float indices)
#define A_F    0u             // [2 spl][128 rows][68]
#define B_F    17408u         // [2 buf][2 spl][128 rows][68]
#define C2_F   52224u         // [512]
#define RV_F   52736u         // [2 wn][128]
#define RI_F   52992u         // [2 wn][128] ints
#define SMEM_BYTES (53248u * 4u)   // 212992 B

__device__ __align__(16) float g_bs[2][KCENT][DIM];  // tf32 splits of -2*c
__device__ __align__(16) float g_c2[KCENT];

__device__ __forceinline__ uint32_t f2tf32(float x) {
    uint32_t r; asm("cvt.rna.tf32.f32 %0, %1;" : "=r"(r) : "f"(x)); return r;
}

__device__ __forceinline__ uint32_t smem_u32(const void* p) {
    uint32_t a;
    asm("{ .reg .u64 t; cvta.to.shared.u64 t, %1; cvt.u32.u64 %0, t; }"
        : "=r"(a) : "l"(p));
    return a;
}

__device__ __forceinline__ void mma_tf32(float* c, const uint32_t* a,
                                         const uint32_t* b) {
    asm volatile(
        "mma.sync.aligned.m16n8k8.row.col.f32.tf32.tf32.f32 "
        "{%0,%1,%2,%3}, {%4,%5,%6,%7}, {%8,%9}, {%0,%1,%2,%3};"
        : "+f"(c[0]), "+f"(c[1]), "+f"(c[2]), "+f"(c[3])
        : "r"(a[0]), "r"(a[1]), "r"(a[2]), "r"(a[3]), "r"(b[0]), "r"(b[1]));
}

template <int N>
__device__ __forceinline__ void cp_wait() {
    asm volatile("cp.async.wait_group %0;" :: "n"(N));
}

// ---------------- prep: split -2*centroids (tf32) + ||c||^2 ----------------
__global__ void prep_kernel(const float* __restrict__ cent)
{
    int r = blockIdx.x * blockDim.x + threadIdx.x;
    if (r >= KCENT) return;
    float s = 0.f;
#pragma unroll
    for (int d = 0; d < DIM; d++) {
        float v = cent[r * DIM + d];
        s = fmaf(v, v, s);
        float t = -2.f * v;                          // exact
        float h = __uint_as_float(f2tf32(t));
        float l = __uint_as_float(f2tf32(t - h));
        g_bs[0][r][d] = h;
        g_bs[1][r][d] = l;
    }
    g_c2[r] = s;
}

// ---------------- main kernel ----------------
extern __shared__ float smf[];

__global__ __launch_bounds__(THREADS, 1)
void kmeans_mma_kernel(const float* __restrict__ x,
                       float* __restrict__ out, int n)
{
    const int tid = threadIdx.x;
    const int lid = tid & 31;
    const int wid = tid >> 5;
    const int wm  = wid >> 1;     // 0..3  (M groups of 32 rows)
    const int wn  = wid & 1;      // 0..1  (N halves of 64 cents)
    const int lr  = lid >> 2;     // 0..7
    const int lc  = lid & 3;      // 0..3

    // stage c2 (512 floats)
    {
        float2 v = reinterpret_cast<const float2*>(g_c2)[tid];
        reinterpret_cast<float2*>(smf + C2_F)[tid] = v;
    }

    // stage X splits: row = tid/2, half = tid&1 (32 cols each)
    {
        const int  r2 = tid >> 1, hf = tid & 1;
        const long grow = (long)blockIdx.x * TILE_M + r2;
        const bool v = (grow < n);
        const float4* xr =
            reinterpret_cast<const float4*>(x + (size_t)grow * DIM) + hf * 8;
        const float4 z = make_float4(0.f, 0.f, 0.f, 0.f);
#pragma unroll
        for (int j = 0; j < 8; j++) {
            float4 c = v ? xr[j] : z;
            float a[4] = {c.x, c.y, c.z, c.w};
            float hv[4], lv[4];
#pragma unroll
            for (int q = 0; q < 4; q++) {
                hv[q] = __uint_as_float(f2tf32(a[q]));
                lv[q] = __uint_as_float(f2tf32(a[q] - hv[q]));
            }
            const int col = hf * 32 + j * 4;
            *reinterpret_cast<float4*>(smf + A_F + r2 * 68 + col) =
                make_float4(hv[0], hv[1], hv[2], hv[3]);
            *reinterpret_cast<float4*>(smf + A_F + 8704u + r2 * 68 + col) =
                make_float4(lv[0], lv[1], lv[2], lv[3]);
        }
    }

    // cp.async stage of one B chunk (64 KB: 2 splits x 128 rows x 64 floats)
    auto issueB = [&](int ch, int buf) {
#pragma unroll
        for (int i = 0; i < 16; i++) {
            int it  = tid + i * THREADS;     // 0..4095
            int spl = it >> 11;
            int rem = it & 2047;
            int r   = rem >> 4;
            int q   = rem & 15;
            const float* src = &g_bs[spl][ch * CHN + r][q * 4];
            uint64_t gs;
            asm("cvta.to.global.u64 %0, %1;" : "=l"(gs) : "l"(src));
            uint32_t ds = smem_u32(smf + B_F + (uint32_t)buf * 17408u +
                                   (uint32_t)spl * 8704u + r * 68u + q * 4u);
            asm volatile("cp.async.cg.shared.global [%0], [%1], 16;"
                         :: "r"(ds), "l"(gs));
        }
        asm volatile("cp.async.commit_group;");
    };

    float bv[2][2] = {{3.4e38f, 3.4e38f}, {3.4e38f, 3.4e38f}};
    int   bi[2][2] = {{0, 0}, {0, 0}};

    auto compute = [&](int ch, int buf) {
        const float* A0 = smf + A_F + (wm * 32 + lr) * 68 + lc;          // x_h
        const float* A1 = A0 + 8704;                                     // x_l
        const float* B0 = smf + B_F + (uint32_t)buf * 17408u +
                          (wn * 64 + lr) * 68 + lc;                      // c_h
        const float* B1 = B0 + 8704;                                     // c_l
        const float* c2p = smf + C2_F + ch * CHN + wn * 64 + 2 * lc;

        float acc[2][8][4];
#pragma unroll
        for (int nt = 0; nt < 8; nt++) {
            float2 cc = *reinterpret_cast<const float2*>(c2p + nt * 8);
#pragma unroll
            for (int mt = 0; mt < 2; mt++) {
                acc[mt][nt][0] = cc.x; acc[mt][nt][1] = cc.y;
                acc[mt][nt][2] = cc.x; acc[mt][nt][3] = cc.y;
            }
        }

#pragma unroll
        for (int s = 0; s < 8; s++) {
            uint32_t ah[2][4], al[2][4];
#pragma unroll
            for (int mt = 0; mt < 2; mt++) {
                const float* a0 = A0 + mt * (16 * 68) + s * 8;
                ah[mt][0] = __float_as_uint(a0[0]);
                ah[mt][1] = __float_as_uint(a0[8 * 68]);
                ah[mt][2] = __float_as_uint(a0[4]);
                ah[mt][3] = __float_as_uint(a0[8 * 68 + 4]);
                const float* a1 = A1 + mt * (16 * 68) + s * 8;
                al[mt][0] = __float_as_uint(a1[0]);
                al[mt][1] = __float_as_uint(a1[8 * 68]);
                al[mt][2] = __float_as_uint(a1[4]);
                al[mt][3] = __float_as_uint(a1[8 * 68 + 4]);
            }
#pragma unroll
            for (int nt = 0; nt < 8; nt++) {
                const float* b0 = B0 + nt * (8 * 68) + s * 8;
                const float* b1 = B1 + nt * (8 * 68) + s * 8;
                uint32_t bh[2] = {__float_as_uint(b0[0]),
                                  __float_as_uint(b0[4])};
                uint32_t bl[2] = {__float_as_uint(b1[0]),
                                  __float_as_uint(b1[4])};
#pragma unroll
                for (int mt = 0; mt < 2; mt++) {
                    mma_tf32(acc[mt][nt], ah[mt], bh);   // hh
                    mma_tf32(acc[mt][nt], ah[mt], bl);   // hl
                    mma_tf32(acc[mt][nt], al[mt], bh);   // lh
                }
            }
        }

        // running argmin update (ascending idx; strict < = first occurrence)
#pragma unroll
        for (int mt = 0; mt < 2; mt++) {
#pragma unroll
            for (int nt = 0; nt < 8; nt++) {
                const int idx = ch * CHN + wn * 64 + nt * 8 + 2 * lc;
                float v0 = acc[mt][nt][0], v1 = acc[mt][nt][1];
                float v2 = acc[mt][nt][2], v3 = acc[mt][nt][3];
                if (v0 < bv[mt][0]) { bv[mt][0] = v0; bi[mt][0] = idx;     }
                if (v1 < bv[mt][0]) { bv[mt][0] = v1; bi[mt][0] = idx + 1; }
                if (v2 < bv[mt][1]) { bv[mt][1] = v2; bi[mt][1] = idx;     }
                if (v3 < bv[mt][1]) { bv[mt][1] = v3; bi[mt][1] = idx + 1; }
            }
        }
    };

    // pipeline: double-buffered B chunks via cp.async
    issueB(0, 0);
    issueB(1, 1); cp_wait<1>(); __syncthreads();
    compute(0, 0); __syncthreads();
    issueB(2, 0); cp_wait<1>(); __syncthreads();
    compute(1, 1); __syncthreads();
    issueB(3, 1); cp_wait<1>(); __syncthreads();
    compute(2, 0); __syncthreads();
    cp_wait<0>(); __syncthreads();
    compute(3, 1);

    // reduce across the 4-lane col groups (lexicographic for first-occurrence)
#pragma unroll
    for (int mt = 0; mt < 2; mt++) {
#pragma unroll
        for (int h = 0; h < 2; h++) {
#pragma unroll
            for (int d = 1; d <= 2; d <<= 1) {
                float ov = __shfl_xor_sync(0xFFFFFFFFu, bv[mt][h], d);
                int   oi = __shfl_xor_sync(0xFFFFFFFFu, bi[mt][h], d);
                if (ov < bv[mt][h] || (ov == bv[mt][h] && oi < bi[mt][h])) {
                    bv[mt][h] = ov; bi[mt][h] = oi;
                }
            }
        }
    }
    if (lc == 0) {
#pragma unroll
        for (int mt = 0; mt < 2; mt++) {
#pragma unroll
            for (int h = 0; h < 2; h++) {
                int rowl = wm * 32 + mt * 16 + h * 8 + lr;
                smf[RV_F + wn * 128 + rowl] = bv[mt][h];
                reinterpret_cast<int*>(smf)[RI_F + wn * 128 + rowl] = bi[mt][h];
            }
        }
    }
    __syncthreads();

    if (tid < TILE_M) {
        float v0 = smf[RV_F + tid],        v1 = smf[RV_F + 128 + tid];
        int   i0 = reinterpret_cast<int*>(smf)[RI_F + tid];
        int   i1 = reinterpret_cast<int*>(smf)[RI_F + 128 + tid];
        int best = (v1 < v0 || (v1 == v0 && i1 < i0)) ? i1 : i0;
        long grow = (long)blockIdx.x * TILE_M + tid;
        if (grow < n) out[grow] = (float)best;
    }
}

// ---------------- launch ----------------
extern "C" void kernel_launch(void* const* d_in, const int* in_sizes, int n_in,
                              void* d_out, int out_size)
{
    const float* x = (const float*)d_in[0];     // [N, 64] fp32
    const float* c = (const float*)d_in[1];     // [512, 64] fp32
    float* out = (float*)d_out;                 // [N] labels as float

    const int n = in_sizes[0] / DIM;

    cudaFuncSetAttribute(kmeans_mma_kernel,
                         cudaFuncAttributeMaxDynamicSharedMemorySize,
                         SMEM_BYTES);

    prep_kernel<<<4, 128>>>(c);
    const int grid = (n + TILE_M - 1) / TILE_M;
    kmeans_mma_kernel<<<grid, THREADS, SMEM_BYTES>>>(x, out, n);
}

// round 5
// speedup vs baseline: 2.9248x; 1.8595x over previous
#include <cuda_runtime.h>
#include <cuda_fp16.h>
#include <cstdint>

// KMeans labels via legacy fp16 tensor cores (mma.sync m16n8k16, 2x tf32 rate).
// score(i,k) = ||c_k||^2 - 2<x_i,c_k>.  fp32 = h + l fp16 split (11+11 bits).
// Terms: hh + hl + lh (ll ~2^-22 dropped).  Cross terms via exact 2^{+-6}
// operand scaling so one fp32 accumulator works:
//   ah*bl = (ah*2^-6)*(bl*2^6),  al*bh = (al*2^6)*(bh*2^-6).
// Scaled variants computed in-register (HMUL2, exact exponent shift).

#define DIM      64
#define KCENT    512
#define TILE_M   128
#define CHN      128
#define THREADS  256

// dynamic smem byte offsets (XOR-swizzled 128B rows, no padding)
#define SA    0u         // 2 vars * 128 rows * 128B = 32768
#define SB    32768u     // 2 bufs * 2 vars * 16384 = 65536
#define SC2   98304u     // 512 f32
#define SRV   100352u    // 256 f32
#define SRI   101376u    // 256 i32
#define SMEM_BYTES 102400u

__device__ __align__(16) __half g_bh[KCENT][DIM];   // rn16(-2c)
__device__ __align__(16) __half g_bl[KCENT][DIM];   // rn16((-2c - h)*64)
__device__ __align__(16) float  g_c2[KCENT];

__device__ __forceinline__ uint32_t smem_u32(const void* p) {
    uint32_t a;
    asm("{ .reg .u64 t; cvta.to.shared.u64 t, %1; cvt.u32.u64 %0, t; }"
        : "=r"(a) : "l"(p));
    return a;
}

__device__ __forceinline__ uint32_t pack_h2(__half a, __half b) {
    __half2 t = __halves2half2(a, b);
    return *reinterpret_cast<uint32_t*>(&t);
}

__device__ __forceinline__ uint32_t hscale(uint32_t v, __half2 k) {
    __half2 t = __hmul2(*reinterpret_cast<__half2*>(&v), k);
    return *reinterpret_cast<uint32_t*>(&t);
}

__device__ __forceinline__ void ldm_x4(uint32_t* r, uint32_t addr) {
    asm volatile("ldmatrix.sync.aligned.m8n8.x4.shared.b16 {%0,%1,%2,%3}, [%4];"
                 : "=r"(r[0]), "=r"(r[1]), "=r"(r[2]), "=r"(r[3]) : "r"(addr));
}

__device__ __forceinline__ void ldm_x2(uint32_t* r, uint32_t addr) {
    asm volatile("ldmatrix.sync.aligned.m8n8.x2.shared.b16 {%0,%1}, [%2];"
                 : "=r"(r[0]), "=r"(r[1]) : "r"(addr));
}

__device__ __forceinline__ void mma_f16(float* c, const uint32_t* a,
                                        const uint32_t* b) {
    asm volatile(
        "mma.sync.aligned.m16n8k16.row.col.f32.f16.f16.f32 "
        "{%0,%1,%2,%3}, {%4,%5,%6,%7}, {%8,%9}, {%0,%1,%2,%3};"
        : "+f"(c[0]), "+f"(c[1]), "+f"(c[2]), "+f"(c[3])
        : "r"(a[0]), "r"(a[1]), "r"(a[2]), "r"(a[3]), "r"(b[0]), "r"(b[1]));
}

template <int N>
__device__ __forceinline__ void cp_wait() {
    asm volatile("cp.async.wait_group %0;" :: "n"(N));
}

// ---------------- prep: fp16 split of -2*centroids + ||c||^2 ----------------
__global__ void prep_kernel(const float* __restrict__ cent)
{
    int r = blockIdx.x * blockDim.x + threadIdx.x;
    if (r >= KCENT) return;
    float s = 0.f;
#pragma unroll
    for (int d = 0; d < DIM; d++) {
        float c = cent[r * DIM + d];
        s = fmaf(c, c, s);
        float v = -2.f * c;                        // exact
        __half h = __float2half_rn(v);
        g_bh[r][d] = h;
        g_bl[r][d] = __float2half_rn((v - __half2float(h)) * 64.f);
    }
    g_c2[r] = s;
}

// ---------------- main kernel ----------------
extern __shared__ char smc[];

__global__ __launch_bounds__(THREADS, 2)
void kmeans_mma_kernel(const float* __restrict__ x,
                       float* __restrict__ out, int n)
{
    const int tid = threadIdx.x;
    const int lid = tid & 31;
    const int wid = tid >> 5;
    const int wm  = wid >> 1;     // 0..3  M groups of 32
    const int wn  = wid & 1;      // 0..1  N halves of 64
    const int lr  = lid >> 2;     // 0..7
    const int lc  = lid & 3;      // 0..3

    const uint32_t smb = smem_u32(smc);
    const __half2 KSC = __float2half2_rn(0.015625f);   // 2^-6

    // stage c2 (512 floats)
    {
        float2 v = reinterpret_cast<const float2*>(g_c2)[tid];
        reinterpret_cast<float2*>(smc + SC2)[tid] = v;
    }

    // stage A (fp16 split, swizzled): row = tid/2, half = tid&1 (32 cols)
    {
        const int  r2 = tid >> 1, hf = tid & 1;
        const long grow = (long)blockIdx.x * TILE_M + r2;
        const bool vld = (grow < n);
        const float4* xr =
            reinterpret_cast<const float4*>(x + (size_t)grow * DIM) + hf * 8;
        const float4 z = make_float4(0.f, 0.f, 0.f, 0.f);
        const int rs = r2 & 7;
#pragma unroll
        for (int j = 0; j < 8; j++) {
            float4 c = vld ? xr[j] : z;
            float a[4] = {c.x, c.y, c.z, c.w};
            __half h[4], l[4];
#pragma unroll
            for (int q = 0; q < 4; q++) {
                h[q] = __float2half_rn(a[q]);
                l[q] = __float2half_rn((a[q] - __half2float(h[q])) * 64.f);
            }
            const int colb = hf * 64 + j * 8;       // byte col within row
            const int qidx = colb >> 4;
            const uint32_t off =
                (uint32_t)r2 * 128u + (uint32_t)((qidx ^ rs) << 4) +
                (uint32_t)(colb & 15);
            *reinterpret_cast<uint2*>(smc + SA + off) =
                make_uint2(pack_h2(h[0], h[1]), pack_h2(h[2], h[3]));
            *reinterpret_cast<uint2*>(smc + SA + 16384u + off) =
                make_uint2(pack_h2(l[0], l[1]), pack_h2(l[2], l[3]));
        }
    }

    // precomputed lane addressing
    const int La   = lid;
    const int arow = ((La >> 3) & 1) * 8 + (La & 7);
    const int aq0  = La >> 4;
    const int asw  = La & 7;
    uint32_t a_base[2][2];
#pragma unroll
    for (int v = 0; v < 2; v++)
#pragma unroll
        for (int mt = 0; mt < 2; mt++)
            a_base[v][mt] = smb + SA + (uint32_t)v * 16384u +
                            (uint32_t)(wm * 32 + mt * 16 + arow) * 128u;

    const int Lb   = lid & 15;
    const int brow = Lb & 7;
    const int bq0  = Lb >> 3;
    uint32_t b_base[2];
#pragma unroll
    for (int v = 0; v < 2; v++)
        b_base[v] = smb + SB + (uint32_t)v * 16384u +
                    (uint32_t)(wn * 64 + brow) * 128u;

    auto issueB = [&](int ch, int buf) {
#pragma unroll
        for (int i = 0; i < 8; i++) {
            int it  = tid + i * THREADS;          // 0..2047
            int var = it >> 10;
            int rem = it & 1023;
            int r   = rem >> 3;
            int q   = rem & 7;
            const __half* src = var ? &g_bl[ch * CHN + r][q * 8]
                                    : &g_bh[ch * CHN + r][q * 8];
            uint64_t gs;
            asm("cvta.to.global.u64 %0, %1;" : "=l"(gs) : "l"(src));
            uint32_t ds = smb + SB + (uint32_t)buf * 32768u +
                          (uint32_t)var * 16384u + (uint32_t)r * 128u +
                          (uint32_t)((q ^ (r & 7)) << 4);
            asm volatile("cp.async.cg.shared.global [%0], [%1], 16;"
                         :: "r"(ds), "l"(gs));
        }
        asm volatile("cp.async.commit_group;");
    };

    float bv[2][2] = {{3.4e38f, 3.4e38f}, {3.4e38f, 3.4e38f}};
    int   bi[2][2] = {{0, 0}, {0, 0}};

    auto compute = [&](int ch, int buf) {
        float acc[2][8][4];
        const float* c2s =
            reinterpret_cast<const float*>(smc + SC2) + ch * CHN + wn * 64 + 2 * lc;
#pragma unroll
        for (int nt = 0; nt < 8; nt++) {
            float2 cc = *reinterpret_cast<const float2*>(c2s + nt * 8);
#pragma unroll
            for (int mt = 0; mt < 2; mt++) {
                acc[mt][nt][0] = cc.x; acc[mt][nt][1] = cc.y;
                acc[mt][nt][2] = cc.x; acc[mt][nt][3] = cc.y;
            }
        }

        const uint32_t bufoff = (uint32_t)buf * 32768u;
#pragma unroll
        for (int s = 0; s < 4; s++) {
            uint32_t ah[2][4], al[2][4], ahs[2][4];
            const uint32_t aoff = (uint32_t)(((2 * s + aq0) ^ asw) << 4);
#pragma unroll
            for (int mt = 0; mt < 2; mt++) {
                ldm_x4(ah[mt], a_base[0][mt] + aoff);
                ldm_x4(al[mt], a_base[1][mt] + aoff);
#pragma unroll
                for (int r = 0; r < 4; r++) ahs[mt][r] = hscale(ah[mt][r], KSC);
            }
            const uint32_t boff = (uint32_t)(((2 * s + bq0) ^ brow) << 4) + bufoff;
#pragma unroll
            for (int nt = 0; nt < 8; nt++) {
                uint32_t bh[2], bl[2], bhs[2];
                const uint32_t ro = (uint32_t)(nt * 8) * 128u + boff;
                ldm_x2(bh, b_base[0] + ro);
                ldm_x2(bl, b_base[1] + ro);
                bhs[0] = hscale(bh[0], KSC);
                bhs[1] = hscale(bh[1], KSC);
#pragma unroll
                for (int mt = 0; mt < 2; mt++) {
                    mma_f16(acc[mt][nt], ah[mt],  bh);   // hh
                    mma_f16(acc[mt][nt], ahs[mt], bl);   // h*l
                    mma_f16(acc[mt][nt], al[mt],  bhs);  // l*h
                }
            }
        }

        // running argmin (ascending idx; strict < = first occurrence)
#pragma unroll
        for (int mt = 0; mt < 2; mt++) {
#pragma unroll
            for (int nt = 0; nt < 8; nt++) {
                const int idx = ch * CHN + wn * 64 + nt * 8 + 2 * lc;
                float v0 = acc[mt][nt][0], v1 = acc[mt][nt][1];
                float v2 = acc[mt][nt][2], v3 = acc[mt][nt][3];
                if (v0 < bv[mt][0]) { bv[mt][0] = v0; bi[mt][0] = idx;     }
                if (v1 < bv[mt][0]) { bv[mt][0] = v1; bi[mt][0] = idx + 1; }
                if (v2 < bv[mt][1]) { bv[mt][1] = v2; bi[mt][1] = idx;     }
                if (v3 < bv[mt][1]) { bv[mt][1] = v3; bi[mt][1] = idx + 1; }
            }
        }
    };

    // pipeline: double-buffered B chunks via cp.async
    issueB(0, 0);
    issueB(1, 1); cp_wait<1>(); __syncthreads();
    compute(0, 0); __syncthreads();
    issueB(2, 0); cp_wait<1>(); __syncthreads();
    compute(1, 1); __syncthreads();
    issueB(3, 1); cp_wait<1>(); __syncthreads();
    compute(2, 0); __syncthreads();
    cp_wait<0>(); __syncthreads();
    compute(3, 1);

    // reduce over the 4-lane column groups (lexicographic: first occurrence)
#pragma unroll
    for (int mt = 0; mt < 2; mt++) {
#pragma unroll
        for (int h = 0; h < 2; h++) {
#pragma unroll
            for (int d = 1; d <= 2; d <<= 1) {
                float ov = __shfl_xor_sync(0xFFFFFFFFu, bv[mt][h], d);
                int   oi = __shfl_xor_sync(0xFFFFFFFFu, bi[mt][h], d);
                if (ov < bv[mt][h] || (ov == bv[mt][h] && oi < bi[mt][h])) {
                    bv[mt][h] = ov; bi[mt][h] = oi;
                }
            }
        }
    }
    if (lc == 0) {
#pragma unroll
        for (int mt = 0; mt < 2; mt++) {
#pragma unroll
            for (int h = 0; h < 2; h++) {
                int rowl = wm * 32 + mt * 16 + h * 8 + lr;
                reinterpret_cast<float*>(smc + SRV)[wn * 128 + rowl] = bv[mt][h];
                reinterpret_cast<int*>(smc + SRI)[wn * 128 + rowl]   = bi[mt][h];
            }
        }
    }
    __syncthreads();

    if (tid < TILE_M) {
        float v0 = reinterpret_cast<float*>(smc + SRV)[tid];
        float v1 = reinterpret_cast<float*>(smc + SRV)[128 + tid];
        int   i0 = reinterpret_cast<int*>(smc + SRI)[tid];
        int   i1 = reinterpret_cast<int*>(smc + SRI)[128 + tid];
        int best = (v1 < v0 || (v1 == v0 && i1 < i0)) ? i1 : i0;
        long grow = (long)blockIdx.x * TILE_M + tid;
        if (grow < n) out[grow] = (float)best;
    }
}

// ---------------- launch ----------------
extern "C" void kernel_launch(void* const* d_in, const int* in_sizes, int n_in,
                              void* d_out, int out_size)
{
    const float* x = (const float*)d_in[0];     // [N, 64] fp32
    const float* c = (const float*)d_in[1];     // [512, 64] fp32
    float* out = (float*)d_out;                 // [N] labels as float

    const int n = in_sizes[0] / DIM;

    cudaFuncSetAttribute(kmeans_mma_kernel,
                         cudaFuncAttributeMaxDynamicSharedMemorySize,
                         SMEM_BYTES);

    prep_kernel<<<4, 128>>>(c);
    const int grid = (n + TILE_M - 1) / TILE_M;
    kmeans_mma_kernel<<<grid, THREADS, SMEM_BYTES>>>(x, out, n);
}

// round 6
// speedup vs baseline: 2.9938x; 1.0236x over previous
#include <cuda_runtime.h>
#include <cuda_fp16.h>
#include <cstdint>

// KMeans labels via legacy fp16 tensor cores (mma.sync m16n8k16).
// score(i,k) = ||c_k||^2 - 2<x_i,c_k>.  fp32 = h + l fp16 split, l at
// NATURAL scale (subnormal-safe: dropped mass < 2^-24).  Terms hh+hl+lh.
// No runtime operand scaling; B fragments loaded 2-at-a-time via ldmatrix.x4.

#define DIM      64
#define KCENT    512
#define TILE_M   128
#define CHN      128
#define THREADS  256

// dynamic smem byte offsets (XOR-swizzled 128B rows, no padding)
#define SA    0u         // 2 vars * 128 rows * 128B = 32768
#define SB    32768u     // 2 bufs * 2 vars * 16384 = 65536
#define SC2   98304u     // 512 f32
#define SRV   100352u    // 256 f32
#define SRI   101376u    // 256 i32
#define SMEM_BYTES 102400u

__device__ __align__(16) __half g_bh[KCENT][DIM];   // rn16(-2c)
__device__ __align__(16) __half g_bl[KCENT][DIM];   // rn16(-2c - h), natural
__device__ __align__(16) float  g_c2[KCENT];

__device__ __forceinline__ uint32_t smem_u32(const void* p) {
    uint32_t a;
    asm("{ .reg .u64 t; cvta.to.shared.u64 t, %1; cvt.u32.u64 %0, t; }"
        : "=r"(a) : "l"(p));
    return a;
}

__device__ __forceinline__ uint32_t pack_h2(__half a, __half b) {
    __half2 t = __halves2half2(a, b);
    return *reinterpret_cast<uint32_t*>(&t);
}

__device__ __forceinline__ void ldm_x4(uint32_t* r, uint32_t addr) {
    asm volatile("ldmatrix.sync.aligned.m8n8.x4.shared.b16 {%0,%1,%2,%3}, [%4];"
                 : "=r"(r[0]), "=r"(r[1]), "=r"(r[2]), "=r"(r[3]) : "r"(addr));
}

__device__ __forceinline__ void mma_f16(float* c, const uint32_t* a,
                                        const uint32_t* b) {
    asm volatile(
        "mma.sync.aligned.m16n8k16.row.col.f32.f16.f16.f32 "
        "{%0,%1,%2,%3}, {%4,%5,%6,%7}, {%8,%9}, {%0,%1,%2,%3};"
        : "+f"(c[0]), "+f"(c[1]), "+f"(c[2]), "+f"(c[3])
        : "r"(a[0]), "r"(a[1]), "r"(a[2]), "r"(a[3]), "r"(b[0]), "r"(b[1]));
}

template <int N>
__device__ __forceinline__ void cp_wait() {
    asm volatile("cp.async.wait_group %0;" :: "n"(N));
}

// ---------------- prep: fp16 split of -2*centroids + ||c||^2 ----------------
__global__ void prep_kernel(const float* __restrict__ cent)
{
    int r = blockIdx.x * blockDim.x + threadIdx.x;
    if (r >= KCENT) return;
    float s = 0.f;
#pragma unroll
    for (int d = 0; d < DIM; d++) {
        float c = cent[r * DIM + d];
        s = fmaf(c, c, s);
        float v = -2.f * c;                        // exact
        __half h = __float2half_rn(v);
        g_bh[r][d] = h;
        g_bl[r][d] = __float2half_rn(v - __half2float(h));   // natural scale
    }
    g_c2[r] = s;
}

// ---------------- main kernel ----------------
extern __shared__ char smc[];

__global__ __launch_bounds__(THREADS, 2)
void kmeans_mma_kernel(const float* __restrict__ x,
                       float* __restrict__ out, int n)
{
    const int tid = threadIdx.x;
    const int lid = tid & 31;
    const int wid = tid >> 5;
    const int wm  = wid >> 1;     // 0..3  M groups of 32
    const int wn  = wid & 1;      // 0..1  N halves of 64
    const int lr  = lid >> 2;     // 0..7
    const int lc  = lid & 3;      // 0..3

    const uint32_t smb = smem_u32(smc);

    // stage c2 (512 floats)
    {
        float2 v = reinterpret_cast<const float2*>(g_c2)[tid];
        reinterpret_cast<float2*>(smc + SC2)[tid] = v;
    }

    // stage A (fp16 split, swizzled): row = tid/2, half = tid&1 (32 cols)
    {
        const int  r2 = tid >> 1, hf = tid & 1;
        const long grow = (long)blockIdx.x * TILE_M + r2;
        const bool vld = (grow < n);
        const float4* xr =
            reinterpret_cast<const float4*>(x + (size_t)grow * DIM) + hf * 8;
        const float4 z = make_float4(0.f, 0.f, 0.f, 0.f);
        const int rs = r2 & 7;
#pragma unroll
        for (int j = 0; j < 8; j++) {
            float4 c = vld ? xr[j] : z;
            float a[4] = {c.x, c.y, c.z, c.w};
            __half h[4], l[4];
#pragma unroll
            for (int q = 0; q < 4; q++) {
                h[q] = __float2half_rn(a[q]);
                l[q] = __float2half_rn(a[q] - __half2float(h[q]));  // natural
            }
            const int colb = hf * 64 + j * 8;       // byte col within row
            const int qidx = colb >> 4;
            const uint32_t off =
                (uint32_t)r2 * 128u + (uint32_t)((qidx ^ rs) << 4) +
                (uint32_t)(colb & 15);
            *reinterpret_cast<uint2*>(smc + SA + off) =
                make_uint2(pack_h2(h[0], h[1]), pack_h2(h[2], h[3]));
            *reinterpret_cast<uint2*>(smc + SA + 16384u + off) =
                make_uint2(pack_h2(l[0], l[1]), pack_h2(l[2], l[3]));
        }
    }

    // A lane addressing (ldmatrix x4: m16 x k16)
    const int arow = ((lid >> 3) & 1) * 8 + (lid & 7);
    const int aq0  = lid >> 4;          // k-quad group
    const int asw  = lid & 7;
    uint32_t a_base[2][2];
#pragma unroll
    for (int v = 0; v < 2; v++)
#pragma unroll
        for (int mt = 0; mt < 2; mt++)
            a_base[v][mt] = smb + SA + (uint32_t)v * 16384u +
                            (uint32_t)(wm * 32 + mt * 16 + arow) * 128u;

    // B lane addressing (ldmatrix x4: two n8k16 fragments per load)
    const int brow = ((lid >> 4) & 1) * 8 + (lid & 7);  // n-row within pair
    const int bq0  = (lid >> 3) & 1;                    // k-quad
    const int bsw  = lid & 7;
    uint32_t b_base[2];
#pragma unroll
    for (int v = 0; v < 2; v++)
        b_base[v] = smb + SB + (uint32_t)v * 16384u +
                    (uint32_t)(wn * 64 + brow) * 128u;

    auto issueB = [&](int ch, int buf) {
#pragma unroll
        for (int i = 0; i < 8; i++) {
            int it  = tid + i * THREADS;          // 0..2047
            int var = it >> 10;
            int rem = it & 1023;
            int r   = rem >> 3;
            int q   = rem & 7;
            const __half* src = var ? &g_bl[ch * CHN + r][q * 8]
                                    : &g_bh[ch * CHN + r][q * 8];
            uint64_t gs;
            asm("cvta.to.global.u64 %0, %1;" : "=l"(gs) : "l"(src));
            uint32_t ds = smb + SB + (uint32_t)buf * 32768u +
                          (uint32_t)var * 16384u + (uint32_t)r * 128u +
                          (uint32_t)((q ^ (r & 7)) << 4);
            asm volatile("cp.async.cg.shared.global [%0], [%1], 16;"
                         :: "r"(ds), "l"(gs));
        }
        asm volatile("cp.async.commit_group;");
    };

    float bv[2][2] = {{3.4e38f, 3.4e38f}, {3.4e38f, 3.4e38f}};
    int   bi[2][2] = {{0, 0}, {0, 0}};

    auto compute = [&](int ch, int buf) {
        float acc[2][8][4];
        const float* c2s =
            reinterpret_cast<const float*>(smc + SC2) + ch * CHN + wn * 64 + 2 * lc;
#pragma unroll
        for (int nt = 0; nt < 8; nt++) {
            float2 cc = *reinterpret_cast<const float2*>(c2s + nt * 8);
#pragma unroll
            for (int mt = 0; mt < 2; mt++) {
                acc[mt][nt][0] = cc.x; acc[mt][nt][1] = cc.y;
                acc[mt][nt][2] = cc.x; acc[mt][nt][3] = cc.y;
            }
        }

        const uint32_t bufoff = (uint32_t)buf * 32768u;
#pragma unroll
        for (int s = 0; s < 4; s++) {
            uint32_t ah[2][4], al[2][4];
            const uint32_t aoff = (uint32_t)(((2 * s + aq0) ^ asw) << 4);
#pragma unroll
            for (int mt = 0; mt < 2; mt++) {
                ldm_x4(ah[mt], a_base[0][mt] + aoff);
                ldm_x4(al[mt], a_base[1][mt] + aoff);
            }
            const uint32_t boff = (uint32_t)(((2 * s + bq0) ^ bsw) << 4) + bufoff;
#pragma unroll
            for (int p = 0; p < 4; p++) {          // pairs of n-tiles
                uint32_t bh4[4], bl4[4];
                const uint32_t ro = (uint32_t)(p * 16) * 128u + boff;
                ldm_x4(bh4, b_base[0] + ro);
                ldm_x4(bl4, b_base[1] + ro);
#pragma unroll
                for (int mt = 0; mt < 2; mt++) {
                    mma_f16(acc[mt][2 * p],     ah[mt], bh4);      // hh (nt=2p)
                    mma_f16(acc[mt][2 * p],     ah[mt], bl4);      // hl
                    mma_f16(acc[mt][2 * p],     al[mt], bh4);      // lh
                    mma_f16(acc[mt][2 * p + 1], ah[mt], bh4 + 2);  // hh (nt=2p+1)
                    mma_f16(acc[mt][2 * p + 1], ah[mt], bl4 + 2);  // hl
                    mma_f16(acc[mt][2 * p + 1], al[mt], bh4 + 2);  // lh
                }
            }
        }

        // running argmin (ascending idx; strict < = first occurrence)
#pragma unroll
        for (int mt = 0; mt < 2; mt++) {
#pragma unroll
            for (int nt = 0; nt < 8; nt++) {
                const int idx = ch * CHN + wn * 64 + nt * 8 + 2 * lc;
                float v0 = acc[mt][nt][0], v1 = acc[mt][nt][1];
                float v2 = acc[mt][nt][2], v3 = acc[mt][nt][3];
                if (v0 < bv[mt][0]) { bv[mt][0] = v0; bi[mt][0] = idx;     }
                if (v1 < bv[mt][0]) { bv[mt][0] = v1; bi[mt][0] = idx + 1; }
                if (v2 < bv[mt][1]) { bv[mt][1] = v2; bi[mt][1] = idx;     }
                if (v3 < bv[mt][1]) { bv[mt][1] = v3; bi[mt][1] = idx + 1; }
            }
        }
    };

    // pipeline: double-buffered B chunks via cp.async
    issueB(0, 0);
    issueB(1, 1); cp_wait<1>(); __syncthreads();
    compute(0, 0); __syncthreads();
    issueB(2, 0); cp_wait<1>(); __syncthreads();
    compute(1, 1); __syncthreads();
    issueB(3, 1); cp_wait<1>(); __syncthreads();
    compute(2, 0); __syncthreads();
    cp_wait<0>(); __syncthreads();
    compute(3, 1);

    // reduce over the 4-lane column groups (lexicographic: first occurrence)
#pragma unroll
    for (int mt = 0; mt < 2; mt++) {
#pragma unroll
        for (int h = 0; h < 2; h++) {
#pragma unroll
            for (int d = 1; d <= 2; d <<= 1) {
                float ov = __shfl_xor_sync(0xFFFFFFFFu, bv[mt][h], d);
                int   oi = __shfl_xor_sync(0xFFFFFFFFu, bi[mt][h], d);
                if (ov < bv[mt][h] || (ov == bv[mt][h] && oi < bi[mt][h])) {
                    bv[mt][h] = ov; bi[mt][h] = oi;
                }
            }
        }
    }
    if (lc == 0) {
#pragma unroll
        for (int mt = 0; mt < 2; mt++) {
#pragma unroll
            for (int h = 0; h < 2; h++) {
                int rowl = wm * 32 + mt * 16 + h * 8 + lr;
                reinterpret_cast<float*>(smc + SRV)[wn * 128 + rowl] = bv[mt][h];
                reinterpret_cast<int*>(smc + SRI)[wn * 128 + rowl]   = bi[mt][h];
            }
        }
    }
    __syncthreads();

    if (tid < TILE_M) {
        float v0 = reinterpret_cast<float*>(smc + SRV)[tid];
        float v1 = reinterpret_cast<float*>(smc + SRV)[128 + tid];
        int   i0 = reinterpret_cast<int*>(smc + SRI)[tid];
        int   i1 = reinterpret_cast<int*>(smc + SRI)[128 + tid];
        int best = (v1 < v0 || (v1 == v0 && i1 < i0)) ? i1 : i0;
        long grow = (long)blockIdx.x * TILE_M + tid;
        if (grow < n) out[grow] = (float)best;
    }
}

// ---------------- launch ----------------
extern "C" void kernel_launch(void* const* d_in, const int* in_sizes, int n_in,
                              void* d_out, int out_size)
{
    const float* x = (const float*)d_in[0];     // [N, 64] fp32
    const float* c = (const float*)d_in[1];     // [512, 64] fp32
    float* out = (float*)d_out;                 // [N] labels as float

    const int n = in_sizes[0] / DIM;

    cudaFuncSetAttribute(kmeans_mma_kernel,
                         cudaFuncAttributeMaxDynamicSharedMemorySize,
                         SMEM_BYTES);

    prep_kernel<<<4, 128>>>(c);
    const int grid = (n + TILE_M - 1) / TILE_M;
    kmeans_mma_kernel<<<grid, THREADS, SMEM_BYTES>>>(x, out, n);
}

// round 7
// speedup vs baseline: 3.0255x; 1.0106x over previous
#include <cuda_runtime.h>
#include <cuda_fp16.h>
#include <cstdint>

// KMeans labels via legacy fp16 tensor cores (mma.sync m16n8k16).
// score(i,k) = ||c_k||^2 - 2<x_i,c_k>.  fp32 = h + l fp16 split (natural
// scale l), terms hh+hl+lh.  One 512-thread CTA per SM, TILE_M=256, all
// four B chunks resident in smem (one barrier per chunk), argmin folded
// into the final k-step of the MMA stream.

#define DIM      64
#define KCENT    512
#define TILE_M   256
#define CHN      128
#define NCH      4
#define THREADS  512

// smem byte offsets (XOR-swizzled 128B rows)
#define SA    0u          // 2 vars * 256 rows * 128B = 65536
#define SB    65536u      // 4 ch * 2 vars * 128 rows * 128B = 131072
#define SC2   196608u     // 512 f32
#define SRV   198656u     // 2*256 f32
#define SRI   200704u     // 2*256 i32
#define SMEM_BYTES 202752u

__device__ __align__(16) __half g_bh[KCENT][DIM];   // rn16(-2c)
__device__ __align__(16) __half g_bl[KCENT][DIM];   // rn16(-2c - h)
__device__ __align__(16) float  g_c2[KCENT];

__device__ __forceinline__ uint32_t smem_u32(const void* p) {
    uint32_t a;
    asm("{ .reg .u64 t; cvta.to.shared.u64 t, %1; cvt.u32.u64 %0, t; }"
        : "=r"(a) : "l"(p));
    return a;
}

__device__ __forceinline__ uint32_t pack_h2(__half a, __half b) {
    __half2 t = __halves2half2(a, b);
    return *reinterpret_cast<uint32_t*>(&t);
}

__device__ __forceinline__ void ldm_x4(uint32_t* r, uint32_t addr) {
    asm volatile("ldmatrix.sync.aligned.m8n8.x4.shared.b16 {%0,%1,%2,%3}, [%4];"
                 : "=r"(r[0]), "=r"(r[1]), "=r"(r[2]), "=r"(r[3]) : "r"(addr));
}

__device__ __forceinline__ void mma_f16(float* c, const uint32_t* a,
                                        const uint32_t* b) {
    asm volatile(
        "mma.sync.aligned.m16n8k16.row.col.f32.f16.f16.f32 "
        "{%0,%1,%2,%3}, {%4,%5,%6,%7}, {%8,%9}, {%0,%1,%2,%3};"
        : "+f"(c[0]), "+f"(c[1]), "+f"(c[2]), "+f"(c[3])
        : "r"(a[0]), "r"(a[1]), "r"(a[2]), "r"(a[3]), "r"(b[0]), "r"(b[1]));
}

template <int N>
__device__ __forceinline__ void cp_wait() {
    asm volatile("cp.async.wait_group %0;" :: "n"(N));
}

// ---------------- prep: fp16 split of -2*centroids + ||c||^2 ----------------
__global__ void prep_kernel(const float* __restrict__ cent)
{
    int r = blockIdx.x * blockDim.x + threadIdx.x;
    if (r >= KCENT) return;
    float s = 0.f;
#pragma unroll
    for (int d = 0; d < DIM; d++) {
        float c = cent[r * DIM + d];
        s = fmaf(c, c, s);
        float v = -2.f * c;                        // exact
        __half h = __float2half_rn(v);
        g_bh[r][d] = h;
        g_bl[r][d] = __float2half_rn(v - __half2float(h));
    }
    g_c2[r] = s;
}

// ---------------- main kernel ----------------
extern __shared__ char smc[];

__global__ __launch_bounds__(THREADS, 1)
void kmeans_mma_kernel(const float* __restrict__ x,
                       float* __restrict__ out, int n)
{
    const int tid = threadIdx.x;
    const int lid = tid & 31;
    const int wid = tid >> 5;
    const int wm  = wid >> 1;     // 0..7  M groups of 32
    const int wn  = wid & 1;      // 0..1  N halves of 64
    const int lr  = lid >> 2;     // 0..7
    const int lc  = lid & 3;      // 0..3

    const uint32_t smb = smem_u32(smc);

    // ---- issue ALL B chunk loads up front (4 commit groups) ----
#pragma unroll
    for (int ch = 0; ch < NCH; ch++) {
#pragma unroll
        for (int j = 0; j < 4; j++) {
            int it  = tid + j * THREADS;           // 0..2047
            int var = it >> 10;
            int rem = it & 1023;
            int r   = rem >> 3;
            int q   = rem & 7;
            const __half* src = var ? &g_bl[ch * CHN + r][q * 8]
                                    : &g_bh[ch * CHN + r][q * 8];
            uint64_t gs;
            asm("cvta.to.global.u64 %0, %1;" : "=l"(gs) : "l"(src));
            uint32_t ds = smb + SB + (uint32_t)ch * 32768u +
                          (uint32_t)var * 16384u + (uint32_t)r * 128u +
                          (uint32_t)((q ^ (r & 7)) << 4);
            asm volatile("cp.async.cg.shared.global [%0], [%1], 16;"
                         :: "r"(ds), "l"(gs));
        }
        asm volatile("cp.async.commit_group;");
    }

    // ---- stage c2 (512 floats) ----
    reinterpret_cast<float*>(smc + SC2)[tid] = g_c2[tid];

    // ---- stage A (fp16 split, swizzled): row = tid/2, half = tid&1 ----
    {
        const int  r2 = tid >> 1, hf = tid & 1;
        const int  grow = blockIdx.x * TILE_M + r2;
        const bool vld = (grow < n);
        const float4* xr =
            reinterpret_cast<const float4*>(x + (size_t)grow * DIM) + hf * 8;
        const float4 z = make_float4(0.f, 0.f, 0.f, 0.f);
        const int rs = r2 & 7;
#pragma unroll
        for (int j = 0; j < 8; j++) {
            float4 c = vld ? xr[j] : z;
            float a[4] = {c.x, c.y, c.z, c.w};
            __half h[4], l[4];
#pragma unroll
            for (int q = 0; q < 4; q++) {
                h[q] = __float2half_rn(a[q]);
                l[q] = __float2half_rn(a[q] - __half2float(h[q]));
            }
            const int colb = hf * 64 + j * 8;
            const int qidx = colb >> 4;
            const uint32_t off =
                (uint32_t)r2 * 128u + (uint32_t)((qidx ^ rs) << 4) +
                (uint32_t)(colb & 15);
            *reinterpret_cast<uint2*>(smc + SA + off) =
                make_uint2(pack_h2(h[0], h[1]), pack_h2(h[2], h[3]));
            *reinterpret_cast<uint2*>(smc + SA + 32768u + off) =
                make_uint2(pack_h2(l[0], l[1]), pack_h2(l[2], l[3]));
        }
    }

    // A lane addressing (ldmatrix x4: m16 x k16)
    const int arow = ((lid >> 3) & 1) * 8 + (lid & 7);
    const int aq0  = lid >> 4;
    const int asw  = lid & 7;
    uint32_t a_base[2][2];
#pragma unroll
    for (int v = 0; v < 2; v++)
#pragma unroll
        for (int mt = 0; mt < 2; mt++)
            a_base[v][mt] = smb + SA + (uint32_t)v * 32768u +
                            (uint32_t)(wm * 32 + mt * 16 + arow) * 128u;

    // B lane addressing (ldmatrix x4: two n8k16 fragments per load)
    const int brow = ((lid >> 4) & 1) * 8 + (lid & 7);
    const int bq0  = (lid >> 3) & 1;
    const int bsw  = lid & 7;
    const uint32_t b_row_off = (uint32_t)(wn * 64 + brow) * 128u;

    float bv[2][2] = {{3.4e38f, 3.4e38f}, {3.4e38f, 3.4e38f}};
    int   bi[2][2] = {{0, 0}, {0, 0}};

    auto compute = [&](int ch) {
        float acc[2][8][4];
        const float* c2s =
            reinterpret_cast<const float*>(smc + SC2) + ch * CHN + wn * 64 + 2 * lc;
#pragma unroll
        for (int nt = 0; nt < 8; nt++) {
            float2 cc = *reinterpret_cast<const float2*>(c2s + nt * 8);
#pragma unroll
            for (int mt = 0; mt < 2; mt++) {
                acc[mt][nt][0] = cc.x; acc[mt][nt][1] = cc.y;
                acc[mt][nt][2] = cc.x; acc[mt][nt][3] = cc.y;
            }
        }

        const uint32_t bb0 = smb + SB + (uint32_t)ch * 32768u + b_row_off;
        const uint32_t bb1 = bb0 + 16384u;
        const int idx0 = ch * CHN + wn * 64 + 2 * lc;

#pragma unroll
        for (int s = 0; s < 4; s++) {
            uint32_t ah[2][4], al[2][4];
            const uint32_t aoff = (uint32_t)(((2 * s + aq0) ^ asw) << 4);
#pragma unroll
            for (int mt = 0; mt < 2; mt++) {
                ldm_x4(ah[mt], a_base[0][mt] + aoff);
                ldm_x4(al[mt], a_base[1][mt] + aoff);
            }
            const uint32_t boff = (uint32_t)(((2 * s + bq0) ^ bsw) << 4);
#pragma unroll
            for (int p = 0; p < 4; p++) {
                uint32_t bh4[4], bl4[4];
                const uint32_t ro = (uint32_t)(p * 16) * 128u + boff;
                ldm_x4(bh4, bb0 + ro);
                ldm_x4(bl4, bb1 + ro);
#pragma unroll
                for (int mt = 0; mt < 2; mt++) {
                    mma_f16(acc[mt][2 * p],     ah[mt], bh4);
                    mma_f16(acc[mt][2 * p],     ah[mt], bl4);
                    mma_f16(acc[mt][2 * p],     al[mt], bh4);
                    mma_f16(acc[mt][2 * p + 1], ah[mt], bh4 + 2);
                    mma_f16(acc[mt][2 * p + 1], ah[mt], bl4 + 2);
                    mma_f16(acc[mt][2 * p + 1], al[mt], bh4 + 2);
                }
                if (s == 3) {
                    // accumulators for nt = 2p, 2p+1 are complete: reduce now,
                    // overlapping compares with the remaining p-iterations.
#pragma unroll
                    for (int u = 0; u < 2; u++) {
                        const int nt = 2 * p + u;
                        const int idx = idx0 + nt * 8;
#pragma unroll
                        for (int mt = 0; mt < 2; mt++) {
                            float v0 = acc[mt][nt][0], v1 = acc[mt][nt][1];
                            float v2 = acc[mt][nt][2], v3 = acc[mt][nt][3];
                            if (v0 < bv[mt][0]) { bv[mt][0] = v0; bi[mt][0] = idx;     }
                            if (v1 < bv[mt][0]) { bv[mt][0] = v1; bi[mt][0] = idx + 1; }
                            if (v2 < bv[mt][1]) { bv[mt][1] = v2; bi[mt][1] = idx;     }
                            if (v3 < bv[mt][1]) { bv[mt][1] = v3; bi[mt][1] = idx + 1; }
                        }
                    }
                }
            }
        }
    };

    // ---- pipeline: one wait + one barrier per chunk ----
    cp_wait<3>(); __syncthreads();   // chunk 0 ready; also covers A/c2 stores
    compute(0);
    cp_wait<2>(); __syncthreads();
    compute(1);
    cp_wait<1>(); __syncthreads();
    compute(2);
    cp_wait<0>(); __syncthreads();
    compute(3);

    // reduce over the 4-lane column groups (lexicographic: first occurrence)
#pragma unroll
    for (int mt = 0; mt < 2; mt++) {
#pragma unroll
        for (int h = 0; h < 2; h++) {
#pragma unroll
            for (int d = 1; d <= 2; d <<= 1) {
                float ov = __shfl_xor_sync(0xFFFFFFFFu, bv[mt][h], d);
                int   oi = __shfl_xor_sync(0xFFFFFFFFu, bi[mt][h], d);
                if (ov < bv[mt][h] || (ov == bv[mt][h] && oi < bi[mt][h])) {
                    bv[mt][h] = ov; bi[mt][h] = oi;
                }
            }
        }
    }
    __syncthreads();   // smem reuse: SRV/SRI overlap nothing, but order writes
    if (lc == 0) {
#pragma unroll
        for (int mt = 0; mt < 2; mt++) {
#pragma unroll
            for (int h = 0; h < 2; h++) {
                int rowl = wm * 32 + mt * 16 + h * 8 + lr;
                reinterpret_cast<float*>(smc + SRV)[wn * 256 + rowl] = bv[mt][h];
                reinterpret_cast<int*>(smc + SRI)[wn * 256 + rowl]   = bi[mt][h];
            }
        }
    }
    __syncthreads();

    if (tid < TILE_M) {
        float v0 = reinterpret_cast<float*>(smc + SRV)[tid];
        float v1 = reinterpret_cast<float*>(smc + SRV)[256 + tid];
        int   i0 = reinterpret_cast<int*>(smc + SRI)[tid];
        int   i1 = reinterpret_cast<int*>(smc + SRI)[256 + tid];
        int best = (v1 < v0 || (v1 == v0 && i1 < i0)) ? i1 : i0;
        int grow = blockIdx.x * TILE_M + tid;
        if (grow < n) out[grow] = (float)best;
    }
}

// ---------------- launch ----------------
extern "C" void kernel_launch(void* const* d_in, const int* in_sizes, int n_in,
                              void* d_out, int out_size)
{
    const float* x = (const float*)d_in[0];     // [N, 64] fp32
    const float* c = (const float*)d_in[1];     // [512, 64] fp32
    float* out = (float*)d_out;                 // [N] labels as float

    const int n = in_sizes[0] / DIM;

    cudaFuncSetAttribute(kmeans_mma_kernel,
                         cudaFuncAttributeMaxDynamicSharedMemorySize,
                         SMEM_BYTES);

    prep_kernel<<<4, 128>>>(c);
    const int grid = (n + TILE_M - 1) / TILE_M;
    kmeans_mma_kernel<<<grid, THREADS, SMEM_BYTES>>>(x, out, n);
}